// round 5
// baseline (speedup 1.0000x reference)
#include <cuda_runtime.h>

// PolyMinLayer: minimize degree-6 p(x), damped Newton w/ GD fallback.
// Reference fixed point: p'(x*)=0 (g^2 <= 1e-12) reached well before the
// 100-iteration cap (rel_err was exactly 0.0 across several trajectory
// variants in earlier rounds).
//
// Latency-optimized:
//  Phase 1 (12 iters): exact reference semantics (fresh h, fast divide) —
//    protects the basin-selecting early trajectory.
//  Phase 2 (<=88 iters): h lagged per 8-iter block; step = g * rs with
//    rs precomputed off-path. Per-iter critical path: g(12)+mul(4)+sub(4)=20.

#define GRAD_SQ_TOL 1e-12f

__device__ __forceinline__ float rcp_approx(float v) {
    float r;
    asm("rcp.approx.f32 %0, %1;" : "=f"(r) : "f"(v));
    return r;
}

// p' (6 coeffs lowest-first) via Estrin; path 12 cyc.
__device__ __forceinline__ float eval_g(float x, float a0, float a1, float a2,
                                        float a3, float a4, float a5) {
    float x2 = x * x;
    float q0 = fmaf(a1, x, a0);
    float q1 = fmaf(a2, x2, q0);
    float q2 = fmaf(a4, x, a3);
    float q3 = fmaf(a5, x2, q2);
    float x3 = x2 * x;
    return fmaf(q3, x3, q1);
}

// p'' (5 coeffs lowest-first) via Estrin; path 12 cyc.
__device__ __forceinline__ float eval_h(float x, float b0, float b1, float b2,
                                        float b3, float b4) {
    float x2 = x * x;
    float p1 = fmaf(b1, x, b0);
    float p2 = fmaf(b3, x, b2);
    float q  = fmaf(b4, x2, p2);
    return fmaf(q, x2, p1);
}

__global__ void polymin7_kernel(const float* __restrict__ poly,
                                const float* __restrict__ x_init,
                                float* __restrict__ out) {
    if (threadIdx.x != 0 || blockIdx.x != 0) return;

    const float c1 = poly[1], c2 = poly[2], c3 = poly[3];
    const float c4 = poly[4], c5 = poly[5], c6 = poly[6];

    const float a0 = c1,        a1 = 2.0f * c2, a2 = 3.0f * c3;
    const float a3 = 4.0f * c4, a4 = 5.0f * c5, a5 = 6.0f * c6;
    const float b0 = 2.0f * c2, b1 = 6.0f * c3, b2 = 12.0f * c4;
    const float b3 = 20.0f * c5, b4 = 30.0f * c6;

    float x = x_init[0];
    float g = eval_g(x, a0, a1, a2, a3, a4, a5);
    float g2 = __int_as_float(0x7f800000);  // +inf

    // ---- Phase 1: 12 exact iterations, convergence check every 4 ----
    #pragma unroll 1
    for (int it = 0; it < 12; it += 4) {
        if (g2 <= GRAD_SQ_TOL) { out[0] = x; return; }
        #pragma unroll
        for (int k = 0; k < 4; ++k) {
            float h = eval_h(x, b0, b1, b2, b3, b4);
            float newton = __fdividef(g, h);
            float step = (h > 0.0f) ? newton : 0.1f * g;
            x = x - step;
            g = eval_g(x, a0, a1, a2, a3, a4, a5);
        }
        g2 = g * g;
    }
    if (g2 <= GRAD_SQ_TOL) { out[0] = x; return; }

    // ---- Phase 2: lagged-h blocks of 8 (h/rcp off the critical path) ----
    float h0 = eval_h(x, b0, b1, b2, b3, b4);
    float rs = (h0 > 0.0f) ? rcp_approx(h0) : 0.1f;

    #pragma unroll 1
    for (int it = 0; it < 88; it += 8) {
        float h_mid = h0;
        #pragma unroll
        for (int k = 0; k < 8; ++k) {
            x = x - g * rs;
            g = eval_g(x, a0, a1, a2, a3, a4, a5);
            if (k == 5) h_mid = eval_h(x, b0, b1, b2, b3, b4);
        }
        // Refresh rs for next block; rcp overlaps iterations 6-7 above
        // (dependency-scheduled, no control flow in between).
        float r_new = rcp_approx(h_mid);
        float rs_new = (h_mid > 0.0f) ? r_new : 0.1f;
        g2 = g * g;
        rs = rs_new;
        h0 = h_mid;
        if (g2 <= GRAD_SQ_TOL) break;
    }

    out[0] = x;
}

extern "C" void kernel_launch(void* const* d_in, const int* in_sizes, int n_in,
                              void* d_out, int out_size) {
    const float* poly = (const float*)d_in[0];
    const float* x_init = (const float*)d_in[1];
    float* out = (float*)d_out;
    polymin7_kernel<<<1, 32>>>(poly, x_init, out);
}

// round 6
// speedup vs baseline: 1.0098x; 1.0098x over previous
#include <cuda_runtime.h>

// PolyMinLayer: minimize degree-6 p(x), damped Newton w/ GD fallback,
// matching the JAX reference loop:
//   while (g2 > 1e-12 && it < 100):
//     g=p'(x); h=p''(x); step = h>0 ? g/h : 0.1*g; x-=step; g2=p'(x)^2
//
// Optimizations (all validated to hit the same fp32 fixed point, rel_err 0.0):
//  - carried g (top-of-body g == previous g_new)
//  - Estrin evaluation of p' and p'' (12-cyc dependent chains)
//  - __fdividef (RCP+MUL)
//  - unroll-2 blocks; per block, break when x is bitwise unchanged across
//    the block (fp32 fixed point / ulp 2-cycle => all further reference
//    iterations are no-ops) or g^2 <= tol. Cap of 100 iterations preserved.

#define GRAD_SQ_TOL 1e-12f
#define MAX_ITER 100

// p' (6 coeffs lowest-first) via Estrin; dependent path ~12 cyc.
__device__ __forceinline__ float eval_g(float x, float a0, float a1, float a2,
                                        float a3, float a4, float a5) {
    float x2 = x * x;
    float q0 = fmaf(a1, x, a0);
    float q1 = fmaf(a2, x2, q0);
    float q2 = fmaf(a4, x, a3);
    float q3 = fmaf(a5, x2, q2);
    float x3 = x2 * x;
    return fmaf(q3, x3, q1);
}

// p'' (5 coeffs lowest-first) via Estrin; dependent path ~12 cyc.
__device__ __forceinline__ float eval_h(float x, float b0, float b1, float b2,
                                        float b3, float b4) {
    float x2 = x * x;
    float p1 = fmaf(b1, x, b0);
    float p2 = fmaf(b3, x, b2);
    float q  = fmaf(b4, x2, p2);
    return fmaf(q, x2, p1);
}

__global__ void polymin7_kernel(const float* __restrict__ poly,
                                const float* __restrict__ x_init,
                                float* __restrict__ out) {
    if (threadIdx.x != 0 || blockIdx.x != 0) return;

    const float c1 = poly[1], c2 = poly[2], c3 = poly[3];
    const float c4 = poly[4], c5 = poly[5], c6 = poly[6];

    const float a0 = c1,         a1 = 2.0f * c2,  a2 = 3.0f * c3;
    const float a3 = 4.0f * c4,  a4 = 5.0f * c5,  a5 = 6.0f * c6;
    const float b0 = 2.0f * c2,  b1 = 6.0f * c3,  b2 = 12.0f * c4;
    const float b3 = 20.0f * c5, b4 = 30.0f * c6;

    float x = x_init[0];
    float g = eval_g(x, a0, a1, a2, a3, a4, a5);
    float g2 = __int_as_float(0x7f800000);  // +inf: first block always runs

    #pragma unroll 1
    for (int it = 0; it < MAX_ITER; it += 2) {
        if (g2 <= GRAD_SQ_TOL) break;
        float xs = x;  // block-entry x for stagnation detection

        #pragma unroll
        for (int k = 0; k < 2; ++k) {
            float h = eval_h(x, b0, b1, b2, b3, b4);
            float newton = __fdividef(g, h);
            float step = (h > 0.0f) ? newton : 0.1f * g;
            x = x - step;
            g = eval_g(x, a0, a1, a2, a3, a4, a5);
        }
        g2 = g * g;
        // Fixed-point exit: x unchanged across the whole block means every
        // remaining reference iteration is a no-op (or ulp 2-cycle).
        if (x == xs) break;
    }

    out[0] = x;
}

extern "C" void kernel_launch(void* const* d_in, const int* in_sizes, int n_in,
                              void* d_out, int out_size) {
    const float* poly = (const float*)d_in[0];
    const float* x_init = (const float*)d_in[1];
    float* out = (float*)d_out;
    polymin7_kernel<<<1, 32>>>(poly, x_init, out);
}

// round 7
// speedup vs baseline: 1.0248x; 1.0149x over previous
#include <cuda_runtime.h>

// PolyMinLayer: minimize degree-6 p(x), damped Newton w/ GD fallback.
// Reference:
//   while (g2 > 1e-12 && it < 100):
//     g=p'(x); h=p''(x); step = h>0 ? g/h : 0.1*g; x-=step; g2=p'(x)^2
//
// Phase 1 (12 iters): bit-faithful reference dynamics (fresh h, select,
//   fast divide) — protects basin selection.
// Phase 2: software-pipelined. Step scale s = (h>0 ? 1/h : 0.1) is computed
//   from the block-entry x and used for the NEXT block of 2 iterations
//   (lag 2-3). Loop-carried path per iteration: g-Estrin(12)+mul(4)+sub(4)
//   = 20 cyc; h/rcp/select hide under it. Exits (g^2<=tol, x stagnation,
//   100-iteration cap) all hang off the carried chain.

#define GRAD_SQ_TOL 1e-12f

__device__ __forceinline__ float rcp_approx(float v) {
    float r;
    asm("rcp.approx.f32 %0, %1;" : "=f"(r) : "f"(v));
    return r;
}

// p' (6 coeffs lowest-first), Estrin, dependent path ~12 cyc.
__device__ __forceinline__ float eval_g(float x, float a0, float a1, float a2,
                                        float a3, float a4, float a5) {
    float x2 = x * x;
    float q0 = fmaf(a1, x, a0);
    float q1 = fmaf(a2, x2, q0);
    float q2 = fmaf(a4, x, a3);
    float q3 = fmaf(a5, x2, q2);
    float x3 = x2 * x;
    return fmaf(q3, x3, q1);
}

// p'' (5 coeffs lowest-first), Estrin, dependent path ~12 cyc.
__device__ __forceinline__ float eval_h(float x, float b0, float b1, float b2,
                                        float b3, float b4) {
    float x2 = x * x;
    float p1 = fmaf(b1, x, b0);
    float p2 = fmaf(b3, x, b2);
    float q  = fmaf(b4, x2, p2);
    return fmaf(q, x2, p1);
}

__global__ void polymin7_kernel(const float* __restrict__ poly,
                                const float* __restrict__ x_init,
                                float* __restrict__ out) {
    if (threadIdx.x != 0 || blockIdx.x != 0) return;

    const float c1 = poly[1], c2 = poly[2], c3 = poly[3];
    const float c4 = poly[4], c5 = poly[5], c6 = poly[6];

    const float a0 = c1,         a1 = 2.0f * c2,  a2 = 3.0f * c3;
    const float a3 = 4.0f * c4,  a4 = 5.0f * c5,  a5 = 6.0f * c6;
    const float b0 = 2.0f * c2,  b1 = 6.0f * c3,  b2 = 12.0f * c4;
    const float b3 = 20.0f * c5, b4 = 30.0f * c6;

    float x = x_init[0];
    float g = eval_g(x, a0, a1, a2, a3, a4, a5);
    float g2 = __int_as_float(0x7f800000);  // +inf

    // ---- Phase 1: 12 exact reference iterations, checks off-path ----
    #pragma unroll 1
    for (int it = 0; it < 12; it += 4) {
        if (g2 <= GRAD_SQ_TOL) { out[0] = x; return; }
        #pragma unroll
        for (int k = 0; k < 4; ++k) {
            float h = eval_h(x, b0, b1, b2, b3, b4);
            float newton = __fdividef(g, h);
            float step = (h > 0.0f) ? newton : 0.1f * g;
            x = x - step;
            g = eval_g(x, a0, a1, a2, a3, a4, a5);
        }
        g2 = g * g;
    }
    if (g2 <= GRAD_SQ_TOL) { out[0] = x; return; }

    // ---- Phase 2: pipelined, lag-2 step scale ----
    {
        float h = eval_h(x, b0, b1, b2, b3, b4);
        float s_cur = (h > 0.0f) ? rcp_approx(h) : 0.1f;

        #pragma unroll 1
        for (int it = 0; it < 88; it += 2) {
            float xs = x;
            // s for the next block, from block-entry x (off the carried path;
            // ~33 cyc latency hides under 2 x 20 cyc of iterations below).
            float hn = eval_h(x, b0, b1, b2, b3, b4);
            float s_next = (hn > 0.0f) ? rcp_approx(hn) : 0.1f;

            // Carried chain: x -> g -> x (20 cyc each).
            x = x - g * s_cur;
            g = eval_g(x, a0, a1, a2, a3, a4, a5);
            x = x - g * s_cur;
            g = eval_g(x, a0, a1, a2, a3, a4, a5);

            g2 = g * g;
            s_cur = s_next;
            if (g2 <= GRAD_SQ_TOL || x == xs) break;
        }
    }

    out[0] = x;
}

extern "C" void kernel_launch(void* const* d_in, const int* in_sizes, int n_in,
                              void* d_out, int out_size) {
    const float* poly = (const float*)d_in[0];
    const float* x_init = (const float*)d_in[1];
    float* out = (float*)d_out;
    polymin7_kernel<<<1, 32>>>(poly, x_init, out);
}